// round 4
// baseline (speedup 1.0000x reference)
#include <cuda_runtime.h>
#include <cuda_bf16.h>
#include <math.h>
#include <stdint.h>

#define B_ 32
#define S_ 64
#define T_ 16
#define U_ 1024
#define E_ 256
#define V_ 20200
#define G_ 3072          /* 3*U */
#define VP_ 20224        /* V padded to 64 */
#define NB_ 128          /* persistent grid blocks */

// ---------------- device scratch ----------------
__device__ __align__(16) float d_gxall[S_*B_*G_];           // [s*32+b][3072]
__device__ __align__(16) float d_hbuf[2][B_*U_];            // encoder hidden ping-pong
__device__ __align__(16) float d_hdec[B_*U_];               // decoder hidden
__device__ __align__(16) float d_enc[B_*S_*U_];             // encoded [b][s][u]
__device__ __align__(16) float d_pre[B_*S_*U_];             // W1(encoded)+b1, rows b*64+s
__device__ __align__(16) float d_q[B_*U_];                  // attention query
__device__ __align__(16) float d_sc[B_*S_];                 // scores, row b*64+s
__device__ __align__(16) float d_xcat[B_*(U_+E_)];          // [ctx, Ed[tok]]
__device__ __align__(16) float d_Hall[T_*B_*U_];            // decoder hiddens, rows t*32+b
__device__ __align__(16) float d_logits_alt[T_*B_*V_];
__device__ __align__(16) float d_WhP[U_*G_];                // eWh cols permuted (u*3+g)
__device__ __align__(16) float d_dWxP[(U_+E_)*G_];          // dWx cols permuted
// bf16 split operands (A: [M][3K] row-major;  B: [3K][N] k-major)
__device__ __align__(16) __nv_bfloat16 d_WfT3[(size_t)3*1024*VP_];
__device__ __align__(16) __nv_bfloat16 d_W1T3[3*1024*1024];
__device__ __align__(16) __nv_bfloat16 d_eWxT3[3*256*G_];
__device__ __align__(16) __nv_bfloat16 d_xembS[2048*768];
__device__ __align__(16) __nv_bfloat16 d_encS[(size_t)2048*3072];
__device__ __align__(16) __nv_bfloat16 d_HallS[512*3072];
__device__ unsigned int d_ctr[64];    // [0]=cnt  [32]=gen (separate lines)

__device__ __forceinline__ float sigm(float x) { return 1.f / (1.f + expf(-x)); }

// ---------------- software grid barrier (all NB_ blocks co-resident) ----------------
__device__ __forceinline__ void gbar() {
    __syncthreads();
    if (threadIdx.x == 0) {
        __threadfence();
        unsigned g = atomicAdd(&d_ctr[32], 0u);
        if (atomicAdd(&d_ctr[0], 1u) == NB_ - 1u) {
            d_ctr[0] = 0u;
            __threadfence();
            atomicAdd(&d_ctr[32], 1u);
        } else {
            while (atomicAdd(&d_ctr[32], 0u) == g) { }
        }
        __threadfence();
    }
    __syncthreads();
}

// ---------------- setup kernels ----------------
// permute W[rows][3072] columns: out[k][u*3+g] = W[k][g*1024+u]
__global__ void perm3(const float* __restrict__ W, float* __restrict__ out) {
    int idx = blockIdx.x * 256 + threadIdx.x;
    int k = idx / G_, c = idx - k * G_;
    int u = c / 3, g = c - u * 3;
    out[idx] = W[(size_t)k * G_ + g * U_ + u];
}

// embedding gather + bf16 split rows r=s*32+b -> [hi|lo|hi] over 3*256
__global__ void embed_split(const int* __restrict__ enc_in, const float* __restrict__ Ee) {
    int idx = blockIdx.x * 256 + threadIdx.x;
    int r = idx >> 8, e = idx & 255;
    int s = r >> 5, b = r & 31;
    float x = Ee[(size_t)enc_in[b * S_ + s] * E_ + e];
    __nv_bfloat16 hi = __float2bfloat16(x);
    __nv_bfloat16 lo = __float2bfloat16(x - __bfloat162float(hi));
    size_t base = (size_t)r * 768;
    d_xembS[base + e] = hi; d_xembS[base + 256 + e] = lo; d_xembS[base + 512 + e] = hi;
}

// A [M][K] fp32 -> [M][3K] bf16 = [hi|lo|hi]
__global__ void conv_splitA(const float* __restrict__ A, __nv_bfloat16* __restrict__ out, int kshift) {
    int idx = blockIdx.x * 256 + threadIdx.x;
    int K = 1 << kshift;
    int m = idx >> kshift, k = idx & (K - 1);
    float x = A[idx];
    __nv_bfloat16 hi = __float2bfloat16(x);
    __nv_bfloat16 lo = __float2bfloat16(x - __bfloat162float(hi));
    size_t base = (size_t)m * 3 * K;
    out[base + k] = hi; out[base + K + k] = lo; out[base + 2 * K + k] = hi;
}

// W [K][N] fp32 -> out [3K][NP] bf16 K-major = [hi ; hi ; lo] blocks (streaming, no transpose)
__global__ void conv_splitB_km(const float* __restrict__ W, __nv_bfloat16* __restrict__ out,
                               int K, int N, int NP) {
    int idx = blockIdx.x * 256 + threadIdx.x;
    int k = idx / NP, n = idx - k * NP;
    float x = (n < N) ? W[(size_t)k * N + n] : 0.f;
    __nv_bfloat16 hi = __float2bfloat16(x);
    __nv_bfloat16 lo = __float2bfloat16(x - __bfloat162float(hi));
    size_t p = (size_t)k * NP + n, sK = (size_t)K * NP;
    out[p] = hi; out[sK + p] = hi; out[2 * sK + p] = lo;
}

// ---------------- tensor-core bf16 GEMM ----------------
__device__ __forceinline__ void mma_bf16(float* c, const uint32_t* a, const uint32_t* b) {
    asm volatile("mma.sync.aligned.m16n8k16.row.col.f32.bf16.bf16.f32 "
        "{%0,%1,%2,%3},{%4,%5,%6,%7},{%8,%9},{%0,%1,%2,%3};"
        : "+f"(c[0]), "+f"(c[1]), "+f"(c[2]), "+f"(c[3])
        : "r"(a[0]), "r"(a[1]), "r"(a[2]), "r"(a[3]), "r"(b[0]), "r"(b[1]));
}
__device__ __forceinline__ void ldsm_x4(uint32_t* r, uint32_t addr) {
    asm volatile("ldmatrix.sync.aligned.m8n8.x4.shared.b16 {%0,%1,%2,%3}, [%4];"
        : "=r"(r[0]), "=r"(r[1]), "=r"(r[2]), "=r"(r[3]) : "r"(addr));
}
__device__ __forceinline__ void ldsm_x2_trans(uint32_t* r, uint32_t addr) {
    asm volatile("ldmatrix.sync.aligned.m8n8.x2.trans.shared.b16 {%0,%1}, [%2];"
        : "=r"(r[0]), "=r"(r[1]) : "r"(addr));
}

// C = A'[M,K3] @ B'[K3,N](k-major) + bias ; BM=128 BN=64 BK=32, 256 thr (4m x 2n warps)
// MODE 0: C[gm*ldC+gc]; MODE 1: logits scatter gm=t*32+b -> row b*16+t, stride Nreal
template<int MODE>
__global__ __launch_bounds__(256) void gemm_bf16(
    const __nv_bfloat16* __restrict__ A, const __nv_bfloat16* __restrict__ Bkm,
    const float* __restrict__ bias, float* __restrict__ C,
    int ldC, int Nreal, int K3, int ldB)
{
    __shared__ __nv_bfloat16 As[2][128 * 40];
    __shared__ __nv_bfloat16 Bs[2][32 * 72];
    const int tid = threadIdx.x;
    const int wid = tid >> 5, lane = tid & 31;
    const int gid = lane >> 2, tig = lane & 3;
    const int wm = wid & 3, wn = wid >> 2;
    const int m0 = blockIdx.y * 128, n0 = blockIdx.x * 64;

    const uint32_t asBase = (uint32_t)__cvta_generic_to_shared(&As[0][0]);
    const uint32_t bsBase = (uint32_t)__cvta_generic_to_shared(&Bs[0][0]);
    const int lquad = lane >> 3, l7 = lane & 7, l15 = lane & 15;
    const uint32_t aLane = (uint32_t)((((lquad & 1) * 8 + l7) * 80) + (lquad >> 1) * 16);

    float acc[2][4][4] = {};
    const int nkt = K3 >> 5;

    auto ldglobal = [&](int kt, int buf) {
#pragma unroll
        for (int i = 0; i < 2; i++) {
            int u4 = tid + i * 256;
            int row = u4 >> 2, c4 = u4 & 3;
            *(uint4*)&As[buf][row * 40 + c4 * 8] =
                *(const uint4*)&A[(size_t)(m0 + row) * K3 + kt * 32 + c4 * 8];
        }
        {
            int r = tid >> 3, c8 = tid & 7;
            *(uint4*)&Bs[buf][r * 72 + c8 * 8] =
                *(const uint4*)&Bkm[(size_t)(kt * 32 + r) * ldB + n0 + c8 * 8];
        }
    };

    ldglobal(0, 0);
    __syncthreads();
    for (int kt = 0; kt < nkt; kt++) {
        const int buf = kt & 1;
        if (kt + 1 < nkt) ldglobal(kt + 1, buf ^ 1);
#pragma unroll
        for (int ks = 0; ks < 2; ks++) {
            uint32_t a[2][4], b[4][2];
#pragma unroll
            for (int mi = 0; mi < 2; mi++)
                ldsm_x4(a[mi], asBase + (uint32_t)(buf * 128 * 80) +
                               (uint32_t)((wm * 32 + mi * 16) * 80 + ks * 32) + aLane);
#pragma unroll
            for (int ni = 0; ni < 4; ni++)
                ldsm_x2_trans(b[ni], bsBase + (uint32_t)(buf * 32 * 144) +
                              (uint32_t)(((ks * 16 + l15) * 72 + (wn * 32 + ni * 8)) * 2));
#pragma unroll
            for (int mi = 0; mi < 2; mi++)
#pragma unroll
                for (int ni = 0; ni < 4; ni++)
                    mma_bf16(acc[mi][ni], a[mi], b[ni]);
        }
        __syncthreads();
    }

#pragma unroll
    for (int mi = 0; mi < 2; mi++)
#pragma unroll
        for (int ni = 0; ni < 4; ni++) {
            int gm0 = m0 + wm * 32 + mi * 16 + gid;
            int gc0 = n0 + wn * 32 + ni * 8 + tig * 2;
#pragma unroll
            for (int e = 0; e < 4; e++) {
                int gm = gm0 + (e >> 1) * 8;
                int gc = gc0 + (e & 1);
                float v = acc[mi][ni][e];
                if (MODE == 1) {
                    if (gc < Nreal) {
                        int bb = gm & 31, tt = gm >> 5;
                        C[(size_t)(bb * T_ + tt) * Nreal + gc] = v + bias[gc];
                    }
                } else {
                    C[(size_t)gm * ldC + gc] = v + bias[gc];
                }
            }
        }
}

// ---------------- persistent encoder: 64 GRU steps, Wh slice in smem ----------------
// grid NB_=128, block 128 threads. Block owns 8 u's (24 permuted cols).
// thread: bp=tid&15 -> b0=2*bp (2 batches), ug=tid>>4 -> u=nb*8+ug.
__global__ __launch_bounds__(128) void enc_persist(const float* __restrict__ b_rec) {
    extern __shared__ float sw[];              // [1024][24]
    const int nb = blockIdx.x, tid = threadIdx.x;
    for (int i = tid; i < 1024 * 24; i += 128) {
        int k = i / 24, c = i - k * 24;
        sw[i] = d_WhP[(size_t)k * G_ + nb * 24 + c];
    }
    const int bp = tid & 15, ug = tid >> 4;
    const int b0 = bp * 2;
    const int u = nb * 8 + ug;
    const int cg = ug * 3;
    const float brz = b_rec[u], brr = b_rec[U_ + u], brc = b_rec[2 * U_ + u];
    float hreg[2] = {0.f, 0.f};
    __syncthreads();

    for (int s = 0; s < S_; s++) {
        float acc[2][3] = {};
        if (s > 0) {
            const float* hA = d_hbuf[s & 1] + b0 * U_;
            const float* hB = hA + U_;
#pragma unroll 4
            for (int k4 = 0; k4 < 256; k4++) {
                float4 ha = *(const float4*)(hA + k4 * 4);
                float4 hb = *(const float4*)(hB + k4 * 4);
                const float* wr = sw + (k4 * 4) * 24 + cg;
                float av[4] = {ha.x, ha.y, ha.z, ha.w};
                float bv[4] = {hb.x, hb.y, hb.z, hb.w};
#pragma unroll
                for (int j = 0; j < 4; j++) {
#pragma unroll
                    for (int g = 0; g < 3; g++) {
                        float wv = wr[j * 24 + g];
                        acc[0][g] += av[j] * wv;
                        acc[1][g] += bv[j] * wv;
                    }
                }
            }
        }
#pragma unroll
        for (int bi = 0; bi < 2; bi++) {
            int b = b0 + bi;
            const float* gx = d_gxall + ((size_t)s * 32 + b) * G_;
            float z = sigm(gx[u] + acc[bi][0] + brz);
            float r = sigm(gx[U_ + u] + acc[bi][1] + brr);
            float c = tanhf(gx[2 * U_ + u] + r * (acc[bi][2] + brc));
            float h = z * hreg[bi] + (1.f - z) * c;
            hreg[bi] = h;
            d_hbuf[(s + 1) & 1][b * U_ + u] = h;
            d_enc[(size_t)b * (S_ * U_) + s * U_ + u] = h;
        }
        gbar();
    }
}

// ---------------- persistent decoder: 16 steps (q, scores, softmax+ctx, GRU) ------
// grid NB_, 128 threads. smem: W2 slice [1024][8] + dWx slice [1280][24] + sc[2048] + red[1024]
__global__ __launch_bounds__(128) void dec_persist(
    const float* __restrict__ W2, const float* __restrict__ b2,
    const float* __restrict__ Va, const float* __restrict__ bvp,
    const float* __restrict__ Ed, const int* __restrict__ teacher,
    const float* __restrict__ db_in, const float* __restrict__ db_rec)
{
    extern __shared__ float sm[];
    float* w2s = sm;                 // 8192
    float* wds = sm + 8192;          // 30720
    float* scs = sm + 8192 + 30720;  // 2048
    float* red = scs + 2048;         // 1024
    const int nb = blockIdx.x, tid = threadIdx.x;

    for (int i = tid; i < 8192; i += 128) {
        int k = i >> 3, c = i & 7;
        w2s[i] = W2[(size_t)k * U_ + nb * 8 + c];
    }
    for (int i = tid; i < 30720; i += 128) {
        int k = i / 24, c = i - k * 24;
        wds[i] = d_dWxP[(size_t)k * G_ + nb * 24 + c];
    }
    const int bp = tid & 15, cq = tid >> 4;      // phase A/C2 mapping
    const int b0 = bp * 2;
    const int u2 = nb * 8 + cq;                  // W2 output col
    const int u = nb * 8 + cq;                   // GRU u (same range)
    const int cg = cq * 3;
    const float b2c = b2[u2];
    const float biz = db_in[u], bir = db_in[U_ + u], bic = db_in[2 * U_ + u];
    const float brz = db_rec[u], brr = db_rec[U_ + u], brc = db_rec[2 * U_ + u];
    const float bv0 = bvp[0];
    __syncthreads();

    for (int t = 0; t < T_; t++) {
        // ---- phase A: q = h @ W2 + b2 ----
        {
            const float* hsrc = (t == 0) ? d_hbuf[0] : d_hdec;
            const float* hA = hsrc + b0 * U_;
            const float* hB = hA + U_;
            float a0 = 0.f, a1 = 0.f;
#pragma unroll 4
            for (int k4 = 0; k4 < 256; k4++) {
                float4 ha = *(const float4*)(hA + k4 * 4);
                float4 hb = *(const float4*)(hB + k4 * 4);
                float av[4] = {ha.x, ha.y, ha.z, ha.w};
                float bvv[4] = {hb.x, hb.y, hb.z, hb.w};
#pragma unroll
                for (int j = 0; j < 4; j++) {
                    float wv = w2s[(k4 * 4 + j) * 8 + cq];
                    a0 += av[j] * wv; a1 += bvv[j] * wv;
                }
            }
            d_q[b0 * U_ + u2] = a0 + b2c;
            d_q[(b0 + 1) * U_ + u2] = a1 + b2c;
        }
        gbar();
        // ---- phase B: scores ----
        {
            const int w = tid >> 5, lane = tid & 31;
#pragma unroll
            for (int rr = 0; rr < 4; rr++) {
                int row = nb * 16 + w * 4 + rr;       // row = b*64+s
                int b = row >> 6;
                const float* pr = d_pre + (size_t)row * U_;
                const float* qq = d_q + b * U_;
                float p = 0.f;
                for (int uu = lane; uu < U_; uu += 32)
                    p += tanhf(pr[uu] + qq[uu]) * Va[uu];
#pragma unroll
                for (int o = 16; o > 0; o >>= 1) p += __shfl_xor_sync(0xffffffffu, p, o);
                if (lane == 0) d_sc[row] = p + bv0;
            }
        }
        gbar();
        // ---- phase C1: softmax + ctx (+ Ed gather) ----
        {
            for (int i = tid; i < 2048; i += 128) scs[i] = d_sc[i];
            __syncthreads();
            if (tid < 32) {
                int b = tid;
                float m = scs[b * 64];
                for (int s = 1; s < 64; s++) m = fmaxf(m, scs[b * 64 + s]);
                float sum = 0.f;
                for (int s = 0; s < 64; s++) { float e = expf(scs[b * 64 + s] - m); scs[b * 64 + s] = e; sum += e; }
                float inv = 1.f / sum;
                for (int s = 0; s < 64; s++) scs[b * 64 + s] *= inv;
            }
            __syncthreads();
#pragma unroll
            for (int r = 0; r < 2; r++) {
                int task = tid + r * 128;
                int b = task & 31, qd = (task >> 5) & 1, sq = task >> 6;
                const float* ep = d_enc + (size_t)b * (S_ * U_) + nb * 8 + qd * 4;
                float4 a = {0.f, 0.f, 0.f, 0.f};
                for (int s = sq * 16; s < sq * 16 + 16; s++) {
                    float p = scs[b * 64 + s];
                    float4 ev = *(const float4*)(ep + (size_t)s * U_);
                    a.x += p * ev.x; a.y += p * ev.y; a.z += p * ev.z; a.w += p * ev.w;
                }
                *(float4*)&red[task * 4] = a;
            }
            __syncthreads();
            if (tid < 64) {
                int b = tid >> 1, qd = tid & 1;
                float4 s0 = *(float4*)&red[((0 * 64) + qd * 32 + b) * 4];
                float4 s1 = *(float4*)&red[((1 * 64) + qd * 32 + b) * 4];
                float4 s2 = *(float4*)&red[((2 * 64) + qd * 32 + b) * 4];
                float4 s3 = *(float4*)&red[((3 * 64) + qd * 32 + b) * 4];
                float4 o = {s0.x + s1.x + s2.x + s3.x, s0.y + s1.y + s2.y + s3.y,
                            s0.z + s1.z + s2.z + s3.z, s0.w + s1.w + s2.w + s3.w};
                *(float4*)&d_xcat[b * (U_ + E_) + nb * 8 + qd * 4] = o;
            }
            if (tid < 64) {
                int gi = nb * 64 + tid;           // 8192 total
                int b = gi >> 8, e = gi & 255;
                int tok = teacher[b * T_ + t];
                d_xcat[b * (U_ + E_) + U_ + e] = Ed[(size_t)tok * E_ + e];
            }
        }
        gbar();
        // ---- phase C2: xcat @ dWx + GRU gate (h0 = 0) ----
        {
            float acc[2][3] = {};
            const float* xA = d_xcat + b0 * (U_ + E_);
            const float* xB = xA + (U_ + E_);
#pragma unroll 4
            for (int k4 = 0; k4 < 320; k4++) {
                float4 ha = *(const float4*)(xA + k4 * 4);
                float4 hb = *(const float4*)(xB + k4 * 4);
                const float* wr = wds + (k4 * 4) * 24 + cg;
                float av[4] = {ha.x, ha.y, ha.z, ha.w};
                float bvv[4] = {hb.x, hb.y, hb.z, hb.w};
#pragma unroll
                for (int j = 0; j < 4; j++) {
#pragma unroll
                    for (int g = 0; g < 3; g++) {
                        float wv = wr[j * 24 + g];
                        acc[0][g] += av[j] * wv;
                        acc[1][g] += bvv[j] * wv;
                    }
                }
            }
#pragma unroll
            for (int bi = 0; bi < 2; bi++) {
                int b = b0 + bi;
                float z = sigm(acc[bi][0] + biz + brz);
                float r = sigm(acc[bi][1] + bir + brr);
                float c = tanhf(acc[bi][2] + bic + r * brc);
                float h = (1.f - z) * c;
                d_hdec[b * U_ + u] = h;
                d_Hall[((size_t)t * 32 + b) * U_ + u] = h;
            }
        }
        gbar();
    }
}

// ---------------- argmax ----------------
__global__ void argmax_k(const float* __restrict__ logits, long long* outI, float* outF, int asFloat)
{
    const int row = blockIdx.x;
    const float* p = logits + (size_t)row * V_;
    const int tid = threadIdx.x;
    float best = -INFINITY; int bi = 0;
    for (int v = tid; v < V_; v += 256) {
        float val = p[v];
        if (val > best) { best = val; bi = v; }
    }
    __shared__ float bvs[256]; __shared__ int bis[256];
    bvs[tid] = best; bis[tid] = bi;
    __syncthreads();
    for (int st = 128; st > 0; st >>= 1) {
        if (tid < st) {
            float ov = bvs[tid + st]; int oi = bis[tid + st];
            if (ov > bvs[tid] || (ov == bvs[tid] && oi < bis[tid])) { bvs[tid] = ov; bis[tid] = oi; }
        }
        __syncthreads();
    }
    if (tid == 0) {
        if (asFloat) outF[row] = (float)bis[0];
        else         outI[row] = (long long)bis[0];
    }
}

// ---------------- launcher ----------------
static float* symaddr(const void* sym) {
    void* p = nullptr;
    cudaGetSymbolAddress(&p, sym);
    return (float*)p;
}

extern "C" void kernel_launch(void* const* d_in, const int* in_sizes, int n_in,
                              void* d_out, int out_size)
{
    const int s0 = (n_in >= 22) ? 4 : 2;
    const int*   enc_in  = (const int*)d_in[0];
    const int*   teacher = (const int*)d_in[1];
    const float* Ee      = (const float*)d_in[s0 + 0];
    const float* eWx     = (const float*)d_in[s0 + 1];
    const float* eWh     = (const float*)d_in[s0 + 2];
    const float* eb_in   = (const float*)d_in[s0 + 3];
    const float* eb_rec  = (const float*)d_in[s0 + 4];
    const float* Ed      = (const float*)d_in[s0 + 5];
    const float* dWx     = (const float*)d_in[s0 + 6];
    const float* db_in   = (const float*)d_in[s0 + 8];
    const float* db_rec  = (const float*)d_in[s0 + 9];
    const float* W1      = (const float*)d_in[s0 + 10];
    const float* b1      = (const float*)d_in[s0 + 11];
    const float* W2      = (const float*)d_in[s0 + 12];
    const float* b2      = (const float*)d_in[s0 + 13];
    const float* Va      = (const float*)d_in[s0 + 14];
    const float* bvp     = (const float*)d_in[s0 + 15];
    const float* Wf      = (const float*)d_in[s0 + 16];
    const float* bf      = (const float*)d_in[s0 + 17];

    float* encp  = symaddr(d_enc);
    float* prep  = symaddr(d_pre);
    float* Hall  = symaddr(d_Hall);
    float* lalt  = symaddr(d_logits_alt);
    float* gxall = symaddr(d_gxall);
    float* WhP   = symaddr(d_WhP);
    float* dWxP  = symaddr(d_dWxP);
    __nv_bfloat16* WfT3;  { void* p; cudaGetSymbolAddress(&p, d_WfT3);  WfT3  = (__nv_bfloat16*)p; }
    __nv_bfloat16* W1T3;  { void* p; cudaGetSymbolAddress(&p, d_W1T3);  W1T3  = (__nv_bfloat16*)p; }
    __nv_bfloat16* eWxT3; { void* p; cudaGetSymbolAddress(&p, d_eWxT3); eWxT3 = (__nv_bfloat16*)p; }
    __nv_bfloat16* xembS; { void* p; cudaGetSymbolAddress(&p, d_xembS); xembS = (__nv_bfloat16*)p; }
    __nv_bfloat16* encS;  { void* p; cudaGetSymbolAddress(&p, d_encS);  encS  = (__nv_bfloat16*)p; }
    __nv_bfloat16* HallS; { void* p; cudaGetSymbolAddress(&p, d_HallS); HallS = (__nv_bfloat16*)p; }

    // output convention
    const long long LOGN = (long long)B_ * T_ * V_;
    float* logits_dst = (float*)d_out;
    long long* predI = nullptr; float* predF = nullptr; int asFloat = 0;
    if ((long long)out_size == LOGN + 512) { predF = (float*)d_out + LOGN; asFloat = 1; }
    else if ((long long)out_size == LOGN + 1024) { predI = (long long*)((float*)d_out + LOGN); }
    else if (out_size == 512) { logits_dst = lalt; predI = (long long*)d_out; }

    cudaFuncSetAttribute(enc_persist, cudaFuncAttributeMaxDynamicSharedMemorySize, 1024 * 24 * 4);
    cudaFuncSetAttribute(dec_persist, cudaFuncAttributeMaxDynamicSharedMemorySize, (8192 + 30720 + 2048 + 1024) * 4);

    // weight prep
    perm3<<<U_ * G_ / 256, 256>>>(eWh, WhP);
    perm3<<<(U_ + E_) * G_ / 256, 256>>>(dWx, dWxP);
    conv_splitB_km<<<(E_ * G_) / 256, 256>>>(eWx, eWxT3, E_, G_, G_);
    conv_splitB_km<<<(U_ * U_) / 256, 256>>>(W1, W1T3, U_, U_, U_);
    conv_splitB_km<<<(U_ * VP_) / 256, 256>>>(Wf, WfT3, U_, V_, VP_);

    // encoder front: embed + gx (all steps, tensor cores)
    embed_split<<<2048, 256>>>(enc_in, Ee);
    gemm_bf16<0><<<dim3(G_ / 64, (S_ * B_) / 128), 256>>>(xembS, eWxT3, eb_in, gxall, G_, G_, 768, G_);

    // persistent encoder (single launch, 64 steps)
    enc_persist<<<NB_, 128, 1024 * 24 * 4>>>(eb_rec);

    // pre_enc = encoded @ W1 + b1
    conv_splitA<<<(B_ * S_ * U_) / 256, 256>>>(encp, encS, 10);
    gemm_bf16<0><<<dim3(U_ / 64, (B_ * S_) / 128), 256>>>(encS, W1T3, b1, prep, U_, U_, 3072, U_);

    // persistent decoder (single launch, 16 steps)
    dec_persist<<<NB_, 128, (8192 + 30720 + 2048 + 1024) * 4>>>(W2, b2, Va, bvp, Ed, teacher, db_in, db_rec);

    // logits = Hall @ Wf + bf
    conv_splitA<<<(T_ * B_ * U_) / 256, 256>>>(Hall, HallS, 10);
    gemm_bf16<1><<<dim3(VP_ / 64, (T_ * B_) / 128), 256>>>(HallS, WfT3, bf, logits_dst, 0, V_, 3072, VP_);

    if (predI || predF) argmax_k<<<T_ * B_, 256>>>(logits_dst, predI, predF, asFloat);
}

// round 5
// speedup vs baseline: 1.1158x; 1.1158x over previous
#include <cuda_runtime.h>
#include <cuda_bf16.h>
#include <math.h>
#include <stdint.h>
#include <string.h>

#define B_ 32
#define S_ 64
#define T_ 16
#define U_ 1024
#define E_ 256
#define V_ 20200
#define G_ 3072          /* 3*U */
#define VP_ 20224        /* V padded to 64 */
#define NB_ 128          /* persistent grid blocks */
#define UGS 3080         /* encoder smem stride per ug (3*1024 + pad8) */
#define WGS 3848         /* decoder dWx smem stride per ug (3*1280 + pad8) */
#define QS_ 1032         /* decoder W2 smem stride per cq (1024 + pad8) */

// ---------------- device scratch ----------------
__device__ __align__(16) float d_gxall[S_*B_*G_];           // [s*32+b][3072]
__device__ __align__(16) float d_hbuf[2][B_*U_];            // encoder hidden ping-pong
__device__ __align__(16) float d_hdec[B_*U_];               // decoder hidden
__device__ __align__(16) float d_enc[B_*S_*U_];             // encoded [b][s][u]
__device__ __align__(16) float d_pre[B_*S_*U_];             // W1(encoded)+b1, rows b*64+s
__device__ __align__(16) float d_q[B_*U_];                  // attention query
__device__ __align__(16) float d_sc[B_*S_];                 // scores, row b*64+s
__device__ __align__(16) float d_xcat[B_*(U_+E_)];          // [ctx, Ed[tok]]
__device__ __align__(16) float d_Hall[T_*B_*U_];            // decoder hiddens, rows t*32+b
__device__ __align__(16) float d_logits_alt[T_*B_*V_];
// bf16 split operands (A: [M][3K] row-major;  B: [3K][N] k-major)
__device__ __align__(16) __nv_bfloat16 d_WfT3[(size_t)3*1024*VP_];
__device__ __align__(16) __nv_bfloat16 d_W1T3[3*1024*1024];
__device__ __align__(16) __nv_bfloat16 d_eWxT3[3*256*G_];
__device__ __align__(16) __nv_bfloat16 d_xembS[2048*768];
__device__ __align__(16) __nv_bfloat16 d_encS[(size_t)2048*3072];
__device__ __align__(16) __nv_bfloat16 d_HallS[512*3072];
__device__ unsigned int d_cnt;
__device__ volatile unsigned int d_gen;

__device__ __forceinline__ float sigm(float x) { return 1.f / (1.f + expf(-x)); }

// packed fp32x2 FMA (Blackwell): d += a * b elementwise on two packed floats
__device__ __forceinline__ void ffma2(unsigned long long& d, unsigned long long a, unsigned long long b) {
    asm("fma.rn.f32x2 %0, %1, %2, %0;" : "+l"(d) : "l"(a), "l"(b));
}
__device__ __forceinline__ float upsum(unsigned long long v) {
    union { unsigned long long u; float2 f; } x; x.u = v;
    return x.f.x + x.f.y;
}

// ---------------- software grid barrier (volatile-load spin, single atomic arrive) --
__device__ __forceinline__ void gbar() {
    __syncthreads();
    if (threadIdx.x == 0) {
        unsigned g = d_gen;
        __threadfence();
        if (atomicAdd(&d_cnt, 1u) == NB_ - 1u) {
            d_cnt = 0u;
            __threadfence();
            d_gen = g + 1u;
        } else {
            while (d_gen == g) __nanosleep(64);
        }
        __threadfence();
    }
    __syncthreads();
}

// ---------------- setup kernels ----------------
// embedding gather + bf16 split rows r=s*32+b -> [hi|lo|hi] over 3*256
__global__ void embed_split(const int* __restrict__ enc_in, const float* __restrict__ Ee) {
    int idx = blockIdx.x * 256 + threadIdx.x;
    int r = idx >> 8, e = idx & 255;
    int s = r >> 5, b = r & 31;
    float x = Ee[(size_t)enc_in[b * S_ + s] * E_ + e];
    __nv_bfloat16 hi = __float2bfloat16(x);
    __nv_bfloat16 lo = __float2bfloat16(x - __bfloat162float(hi));
    size_t base = (size_t)r * 768;
    d_xembS[base + e] = hi; d_xembS[base + 256 + e] = lo; d_xembS[base + 512 + e] = hi;
}

// A [M][K] fp32 -> [M][3K] bf16 = [hi|lo|hi]
__global__ void conv_splitA(const float* __restrict__ A, __nv_bfloat16* __restrict__ out, int kshift) {
    int idx = blockIdx.x * 256 + threadIdx.x;
    int K = 1 << kshift;
    int m = idx >> kshift, k = idx & (K - 1);
    float x = A[idx];
    __nv_bfloat16 hi = __float2bfloat16(x);
    __nv_bfloat16 lo = __float2bfloat16(x - __bfloat162float(hi));
    size_t base = (size_t)m * 3 * K;
    out[base + k] = hi; out[base + K + k] = lo; out[base + 2 * K + k] = hi;
}

// W [K][N] fp32 -> out [3K][NP] bf16 K-major = [hi ; hi ; lo] blocks
__global__ void conv_splitB_km(const float* __restrict__ W, __nv_bfloat16* __restrict__ out,
                               int K, int N, int NP) {
    int idx = blockIdx.x * 256 + threadIdx.x;
    int k = idx / NP, n = idx - k * NP;
    float x = (n < N) ? W[(size_t)k * N + n] : 0.f;
    __nv_bfloat16 hi = __float2bfloat16(x);
    __nv_bfloat16 lo = __float2bfloat16(x - __bfloat162float(hi));
    size_t p = (size_t)k * NP + n, sK = (size_t)K * NP;
    out[p] = hi; out[sK + p] = hi; out[2 * sK + p] = lo;
}

// ---------------- tensor-core bf16 GEMM ----------------
__device__ __forceinline__ void mma_bf16(float* c, const uint32_t* a, const uint32_t* b) {
    asm volatile("mma.sync.aligned.m16n8k16.row.col.f32.bf16.bf16.f32 "
        "{%0,%1,%2,%3},{%4,%5,%6,%7},{%8,%9},{%0,%1,%2,%3};"
        : "+f"(c[0]), "+f"(c[1]), "+f"(c[2]), "+f"(c[3])
        : "r"(a[0]), "r"(a[1]), "r"(a[2]), "r"(a[3]), "r"(b[0]), "r"(b[1]));
}
__device__ __forceinline__ void ldsm_x4(uint32_t* r, uint32_t addr) {
    asm volatile("ldmatrix.sync.aligned.m8n8.x4.shared.b16 {%0,%1,%2,%3}, [%4];"
        : "=r"(r[0]), "=r"(r[1]), "=r"(r[2]), "=r"(r[3]) : "r"(addr));
}
__device__ __forceinline__ void ldsm_x2_trans(uint32_t* r, uint32_t addr) {
    asm volatile("ldmatrix.sync.aligned.m8n8.x2.trans.shared.b16 {%0,%1}, [%2];"
        : "=r"(r[0]), "=r"(r[1]) : "r"(addr));
}

// C = A'[M,K3] @ B'[K3,N](k-major) + bias ; BM=128 BN=64 BK=32, 256 thr (4m x 2n warps)
// MODE 0: C[gm*ldC+gc]; MODE 1: logits scatter gm=t*32+b -> row b*16+t, stride Nreal
template<int MODE>
__global__ __launch_bounds__(256) void gemm_bf16(
    const __nv_bfloat16* __restrict__ A, const __nv_bfloat16* __restrict__ Bkm,
    const float* __restrict__ bias, float* __restrict__ C,
    int ldC, int Nreal, int K3, int ldB)
{
    __shared__ __nv_bfloat16 As[2][128 * 40];
    __shared__ __nv_bfloat16 Bs[2][32 * 72];
    const int tid = threadIdx.x;
    const int wid = tid >> 5, lane = tid & 31;
    const int gid = lane >> 2, tig = lane & 3;
    const int wm = wid & 3, wn = wid >> 2;
    const int m0 = blockIdx.y * 128, n0 = blockIdx.x * 64;

    const uint32_t asBase = (uint32_t)__cvta_generic_to_shared(&As[0][0]);
    const uint32_t bsBase = (uint32_t)__cvta_generic_to_shared(&Bs[0][0]);
    const int lquad = lane >> 3, l7 = lane & 7, l15 = lane & 15;
    const uint32_t aLane = (uint32_t)((((lquad & 1) * 8 + l7) * 80) + (lquad >> 1) * 16);

    float acc[2][4][4] = {};
    const int nkt = K3 >> 5;

    auto ldglobal = [&](int kt, int buf) {
#pragma unroll
        for (int i = 0; i < 2; i++) {
            int u4 = tid + i * 256;
            int row = u4 >> 2, c4 = u4 & 3;
            *(uint4*)&As[buf][row * 40 + c4 * 8] =
                *(const uint4*)&A[(size_t)(m0 + row) * K3 + kt * 32 + c4 * 8];
        }
        {
            int r = tid >> 3, c8 = tid & 7;
            *(uint4*)&Bs[buf][r * 72 + c8 * 8] =
                *(const uint4*)&Bkm[(size_t)(kt * 32 + r) * ldB + n0 + c8 * 8];
        }
    };

    ldglobal(0, 0);
    __syncthreads();
    for (int kt = 0; kt < nkt; kt++) {
        const int buf = kt & 1;
        if (kt + 1 < nkt) ldglobal(kt + 1, buf ^ 1);
#pragma unroll
        for (int ks = 0; ks < 2; ks++) {
            uint32_t a[2][4], b[4][2];
#pragma unroll
            for (int mi = 0; mi < 2; mi++)
                ldsm_x4(a[mi], asBase + (uint32_t)(buf * 128 * 80) +
                               (uint32_t)((wm * 32 + mi * 16) * 80 + ks * 32) + aLane);
#pragma unroll
            for (int ni = 0; ni < 4; ni++)
                ldsm_x2_trans(b[ni], bsBase + (uint32_t)(buf * 32 * 144) +
                              (uint32_t)(((ks * 16 + l15) * 72 + (wn * 32 + ni * 8)) * 2));
#pragma unroll
            for (int mi = 0; mi < 2; mi++)
#pragma unroll
                for (int ni = 0; ni < 4; ni++)
                    mma_bf16(acc[mi][ni], a[mi], b[ni]);
        }
        __syncthreads();
    }

#pragma unroll
    for (int mi = 0; mi < 2; mi++)
#pragma unroll
        for (int ni = 0; ni < 4; ni++) {
            int gm0 = m0 + wm * 32 + mi * 16 + gid;
            int gc0 = n0 + wn * 32 + ni * 8 + tig * 2;
#pragma unroll
            for (int e = 0; e < 4; e++) {
                int gm = gm0 + (e >> 1) * 8;
                int gc = gc0 + (e & 1);
                float v = acc[mi][ni][e];
                if (MODE == 1) {
                    if (gc < Nreal) {
                        int bb = gm & 31, tt = gm >> 5;
                        C[(size_t)(bb * T_ + tt) * Nreal + gc] = v + bias[gc];
                    }
                } else {
                    C[(size_t)gm * ldC + gc] = v + bias[gc];
                }
            }
        }
}

// ---------------- persistent encoder: 64 GRU steps, Wh slice in smem ----------------
// grid NB_=128, 128 threads. Block owns 8 u's; smem layout [ug][gate][k] (k contiguous).
__global__ __launch_bounds__(128) void enc_persist(const float* __restrict__ eWh,
                                                   const float* __restrict__ b_rec) {
    extern __shared__ float sw[];              // 8 * UGS floats
    const int nb = blockIdx.x, tid = threadIdx.x;
    for (int i = tid; i < 24576; i += 128) {
        int k = i / 24, c = i - k * 24;
        int g = c >> 3, ug = c & 7;
        sw[ug * UGS + g * 1024 + k] = eWh[(size_t)k * G_ + g * 1024 + nb * 8 + ug];
    }
    const int bp = tid & 15, ug = tid >> 4;
    const int b0 = bp * 2;
    const int u = nb * 8 + ug;
    const float brz = b_rec[u], brr = b_rec[U_ + u], brc = b_rec[2 * U_ + u];
    const float* swg = sw + ug * UGS;
    float hreg[2] = {0.f, 0.f};
    __syncthreads();

    for (int s = 0; s < S_; s++) {
        unsigned long long acc[2][3] = {};
        if (s > 0) {
            const float* hA = d_hbuf[s & 1] + b0 * U_;
            const float* hB = hA + U_;
#pragma unroll 4
            for (int k4 = 0; k4 < 256; k4++) {
                ulonglong2 a2 = *(const ulonglong2*)(hA + k4 * 4);
                ulonglong2 c2 = *(const ulonglong2*)(hB + k4 * 4);
#pragma unroll
                for (int g = 0; g < 3; g++) {
                    ulonglong2 w2v = *(const ulonglong2*)(swg + g * 1024 + k4 * 4);
                    ffma2(acc[0][g], a2.x, w2v.x); ffma2(acc[0][g], a2.y, w2v.y);
                    ffma2(acc[1][g], c2.x, w2v.x); ffma2(acc[1][g], c2.y, w2v.y);
                }
            }
        }
#pragma unroll
        for (int bi = 0; bi < 2; bi++) {
            int b = b0 + bi;
            const float* gx = d_gxall + ((size_t)s * 32 + b) * G_;
            float az = upsum(acc[bi][0]), ar = upsum(acc[bi][1]), ac = upsum(acc[bi][2]);
            float z = sigm(gx[u] + az + brz);
            float r = sigm(gx[U_ + u] + ar + brr);
            float c = tanhf(gx[2 * U_ + u] + r * (ac + brc));
            float h = z * hreg[bi] + (1.f - z) * c;
            hreg[bi] = h;
            d_hbuf[(s + 1) & 1][b * U_ + u] = h;
            d_enc[(size_t)b * (S_ * U_) + s * U_ + u] = h;
        }
        if (s < S_ - 1) gbar();
    }
}

// ---------------- persistent decoder: 16 steps x (q, scores, softmax+ctx, GRU) ------
__global__ __launch_bounds__(128) void dec_persist(
    const float* __restrict__ W2, const float* __restrict__ b2,
    const float* __restrict__ dWx,
    const float* __restrict__ Va, const float* __restrict__ bvp,
    const float* __restrict__ Ed, const int* __restrict__ teacher,
    const float* __restrict__ db_in, const float* __restrict__ db_rec)
{
    extern __shared__ float sm[];
    float* w2s = sm;                       // 8 * QS_  = 8256
    float* wds = sm + 8 * QS_;             // 8 * WGS  = 30784
    float* scs = wds + 8 * WGS;            // 2048
    float* red = scs + 2048;               // 1024
    const int nb = blockIdx.x, tid = threadIdx.x;

    for (int i = tid; i < 8192; i += 128) {
        int k = i >> 3, cq = i & 7;
        w2s[cq * QS_ + k] = W2[(size_t)k * U_ + nb * 8 + cq];
    }
    for (int i = tid; i < 30720; i += 128) {
        int k = i / 24, c = i - k * 24;
        int g = c >> 3, ug = c & 7;
        wds[ug * WGS + g * 1280 + k] = dWx[(size_t)k * G_ + g * 1024 + nb * 8 + ug];
    }
    const int bp = tid & 15, cq = tid >> 4;
    const int b0 = bp * 2;
    const int u = nb * 8 + cq;
    const float b2c = b2[u];
    const float biz = db_in[u], bir = db_in[U_ + u], bic = db_in[2 * U_ + u];
    const float brz = db_rec[u], brr = db_rec[U_ + u], brc = db_rec[2 * U_ + u];
    const float bv0 = bvp[0];
    const float* swq = w2s + cq * QS_;
    const float* swd = wds + cq * WGS;
    __syncthreads();

    for (int t = 0; t < T_; t++) {
        // ---- phase A: q = h @ W2 + b2 ----
        {
            const float* hsrc = (t == 0) ? d_hbuf[0] : d_hdec;
            const float* hA = hsrc + b0 * U_;
            const float* hB = hA + U_;
            unsigned long long a0 = 0ull, a1 = 0ull;
#pragma unroll 4
            for (int k4 = 0; k4 < 256; k4++) {
                ulonglong2 ha = *(const ulonglong2*)(hA + k4 * 4);
                ulonglong2 hb = *(const ulonglong2*)(hB + k4 * 4);
                ulonglong2 w2v = *(const ulonglong2*)(swq + k4 * 4);
                ffma2(a0, ha.x, w2v.x); ffma2(a0, ha.y, w2v.y);
                ffma2(a1, hb.x, w2v.x); ffma2(a1, hb.y, w2v.y);
            }
            d_q[b0 * U_ + u] = upsum(a0) + b2c;
            d_q[(b0 + 1) * U_ + u] = upsum(a1) + b2c;
        }
        gbar();
        // ---- phase B: scores ----
        {
            const int w = tid >> 5, lane = tid & 31;
#pragma unroll
            for (int rr = 0; rr < 4; rr++) {
                int row = nb * 16 + w * 4 + rr;       // row = b*64+s
                int b = row >> 6;
                const float* pr = d_pre + (size_t)row * U_;
                const float* qq = d_q + b * U_;
                float p = 0.f;
                for (int uu = lane; uu < U_; uu += 32)
                    p += tanhf(pr[uu] + qq[uu]) * Va[uu];
#pragma unroll
                for (int o = 16; o > 0; o >>= 1) p += __shfl_xor_sync(0xffffffffu, p, o);
                if (lane == 0) d_sc[row] = p + bv0;
            }
        }
        gbar();
        // ---- phase C1: softmax + ctx (+ Ed gather) ----
        {
            for (int i = tid; i < 2048; i += 128) scs[i] = d_sc[i];
            __syncthreads();
            if (tid < 32) {
                int b = tid;
                float m = scs[b * 64];
                for (int s = 1; s < 64; s++) m = fmaxf(m, scs[b * 64 + s]);
                float sum = 0.f;
                for (int s = 0; s < 64; s++) { float e = expf(scs[b * 64 + s] - m); scs[b * 64 + s] = e; sum += e; }
                float inv = 1.f / sum;
                for (int s = 0; s < 64; s++) scs[b * 64 + s] *= inv;
            }
            __syncthreads();
#pragma unroll
            for (int r = 0; r < 2; r++) {
                int task = tid + r * 128;
                int b = task & 31, qd = (task >> 5) & 1, sq = task >> 6;
                const float* ep = d_enc + (size_t)b * (S_ * U_) + nb * 8 + qd * 4;
                float4 a = {0.f, 0.f, 0.f, 0.f};
                for (int s = sq * 16; s < sq * 16 + 16; s++) {
                    float p = scs[b * 64 + s];
                    float4 ev = *(const float4*)(ep + (size_t)s * U_);
                    a.x += p * ev.x; a.y += p * ev.y; a.z += p * ev.z; a.w += p * ev.w;
                }
                *(float4*)&red[task * 4] = a;
            }
            __syncthreads();
            if (tid < 64) {
                int b = tid >> 1, qd = tid & 1;
                float4 s0 = *(float4*)&red[((0 * 64) + qd * 32 + b) * 4];
                float4 s1 = *(float4*)&red[((1 * 64) + qd * 32 + b) * 4];
                float4 s2 = *(float4*)&red[((2 * 64) + qd * 32 + b) * 4];
                float4 s3 = *(float4*)&red[((3 * 64) + qd * 32 + b) * 4];
                float4 o = {s0.x + s1.x + s2.x + s3.x, s0.y + s1.y + s2.y + s3.y,
                            s0.z + s1.z + s2.z + s3.z, s0.w + s1.w + s2.w + s3.w};
                *(float4*)&d_xcat[b * (U_ + E_) + nb * 8 + qd * 4] = o;
            }
            if (tid < 64) {
                int gi = nb * 64 + tid;           // 8192 total
                int b = gi >> 8, e = gi & 255;
                int tok = teacher[b * T_ + t];
                d_xcat[b * (U_ + E_) + U_ + e] = Ed[(size_t)tok * E_ + e];
            }
        }
        gbar();
        // ---- phase C2: xcat @ dWx + GRU gate (h0 = 0) ----
        {
            unsigned long long acc[2][3] = {};
            const float* xA = d_xcat + b0 * (U_ + E_);
            const float* xB = xA + (U_ + E_);
#pragma unroll 4
            for (int k4 = 0; k4 < 320; k4++) {
                ulonglong2 ha = *(const ulonglong2*)(xA + k4 * 4);
                ulonglong2 hb = *(const ulonglong2*)(xB + k4 * 4);
#pragma unroll
                for (int g = 0; g < 3; g++) {
                    ulonglong2 w2v = *(const ulonglong2*)(swd + g * 1280 + k4 * 4);
                    ffma2(acc[0][g], ha.x, w2v.x); ffma2(acc[0][g], ha.y, w2v.y);
                    ffma2(acc[1][g], hb.x, w2v.x); ffma2(acc[1][g], hb.y, w2v.y);
                }
            }
#pragma unroll
            for (int bi = 0; bi < 2; bi++) {
                int b = b0 + bi;
                float z = sigm(upsum(acc[bi][0]) + biz + brz);
                float r = sigm(upsum(acc[bi][1]) + bir + brr);
                float c = tanhf(upsum(acc[bi][2]) + bic + r * brc);
                float h = (1.f - z) * c;
                d_hdec[b * U_ + u] = h;
                d_Hall[((size_t)t * 32 + b) * U_ + u] = h;
            }
        }
        if (t < T_ - 1) gbar();
    }
}

// ---------------- argmax ----------------
__global__ void argmax_k(const float* __restrict__ logits, long long* outI, float* outF, int asFloat)
{
    const int row = blockIdx.x;
    const float* p = logits + (size_t)row * V_;
    const int tid = threadIdx.x;
    float best = -INFINITY; int bi = 0;
    for (int v = tid; v < V_; v += 256) {
        float val = p[v];
        if (val > best) { best = val; bi = v; }
    }
    __shared__ float bvs[256]; __shared__ int bis[256];
    bvs[tid] = best; bis[tid] = bi;
    __syncthreads();
    for (int st = 128; st > 0; st >>= 1) {
        if (tid < st) {
            float ov = bvs[tid + st]; int oi = bis[tid + st];
            if (ov > bvs[tid] || (ov == bvs[tid] && oi < bis[tid])) { bvs[tid] = ov; bis[tid] = oi; }
        }
        __syncthreads();
    }
    if (tid == 0) {
        if (asFloat) outF[row] = (float)bis[0];
        else         outI[row] = (long long)bis[0];
    }
}

// ---------------- launcher ----------------
static float* symaddr(const void* sym) {
    void* p = nullptr;
    cudaGetSymbolAddress(&p, sym);
    return (float*)p;
}

extern "C" void kernel_launch(void* const* d_in, const int* in_sizes, int n_in,
                              void* d_out, int out_size)
{
    const int s0 = (n_in >= 22) ? 4 : 2;
    const int*   enc_in  = (const int*)d_in[0];
    const int*   teacher = (const int*)d_in[1];
    const float* Ee      = (const float*)d_in[s0 + 0];
    const float* eWx     = (const float*)d_in[s0 + 1];
    const float* eWh     = (const float*)d_in[s0 + 2];
    const float* eb_in   = (const float*)d_in[s0 + 3];
    const float* eb_rec  = (const float*)d_in[s0 + 4];
    const float* Ed      = (const float*)d_in[s0 + 5];
    const float* dWx     = (const float*)d_in[s0 + 6];
    const float* db_in   = (const float*)d_in[s0 + 8];
    const float* db_rec  = (const float*)d_in[s0 + 9];
    const float* W1      = (const float*)d_in[s0 + 10];
    const float* b1      = (const float*)d_in[s0 + 11];
    const float* W2      = (const float*)d_in[s0 + 12];
    const float* b2      = (const float*)d_in[s0 + 13];
    const float* Va      = (const float*)d_in[s0 + 14];
    const float* bvp     = (const float*)d_in[s0 + 15];
    const float* Wf      = (const float*)d_in[s0 + 16];
    const float* bf      = (const float*)d_in[s0 + 17];

    float* encp  = symaddr(d_enc);
    float* prep  = symaddr(d_pre);
    float* Hall  = symaddr(d_Hall);
    float* lalt  = symaddr(d_logits_alt);
    float* gxall = symaddr(d_gxall);
    __nv_bfloat16* WfT3;  { void* p; cudaGetSymbolAddress(&p, d_WfT3);  WfT3  = (__nv_bfloat16*)p; }
    __nv_bfloat16* W1T3;  { void* p; cudaGetSymbolAddress(&p, d_W1T3);  W1T3  = (__nv_bfloat16*)p; }
    __nv_bfloat16* eWxT3; { void* p; cudaGetSymbolAddress(&p, d_eWxT3); eWxT3 = (__nv_bfloat16*)p; }
    __nv_bfloat16* xembS; { void* p; cudaGetSymbolAddress(&p, d_xembS); xembS = (__nv_bfloat16*)p; }
    __nv_bfloat16* encS;  { void* p; cudaGetSymbolAddress(&p, d_encS);  encS  = (__nv_bfloat16*)p; }
    __nv_bfloat16* HallS; { void* p; cudaGetSymbolAddress(&p, d_HallS); HallS = (__nv_bfloat16*)p; }

    // output convention
    const long long LOGN = (long long)B_ * T_ * V_;
    float* logits_dst = (float*)d_out;
    long long* predI = nullptr; float* predF = nullptr; int asFloat = 0;
    if ((long long)out_size == LOGN + 512) { predF = (float*)d_out + LOGN; asFloat = 1; }
    else if ((long long)out_size == LOGN + 1024) { predI = (long long*)((float*)d_out + LOGN); }
    else if (out_size == 512) { logits_dst = lalt; predI = (long long*)d_out; }

    const int ENC_SMEM = 8 * UGS * 4;
    const int DEC_SMEM = (8 * QS_ + 8 * WGS + 2048 + 1024) * 4;
    cudaFuncSetAttribute(enc_persist, cudaFuncAttributeMaxDynamicSharedMemorySize, ENC_SMEM);
    cudaFuncSetAttribute(dec_persist, cudaFuncAttributeMaxDynamicSharedMemorySize, DEC_SMEM);

    // weight prep (bf16 splits)
    conv_splitB_km<<<(E_ * G_) / 256, 256>>>(eWx, eWxT3, E_, G_, G_);
    conv_splitB_km<<<(U_ * U_) / 256, 256>>>(W1, W1T3, U_, U_, U_);
    conv_splitB_km<<<(U_ * VP_) / 256, 256>>>(Wf, WfT3, U_, V_, VP_);

    // encoder front: embed + gx (all steps, tensor cores)
    embed_split<<<2048, 256>>>(enc_in, Ee);
    gemm_bf16<0><<<dim3(G_ / 64, (S_ * B_) / 128), 256>>>(xembS, eWxT3, eb_in, gxall, G_, G_, 768, G_);

    // persistent encoder (single launch, 64 steps)
    enc_persist<<<NB_, 128, ENC_SMEM>>>(eWh, eb_rec);

    // pre_enc = encoded @ W1 + b1
    conv_splitA<<<(B_ * S_ * U_) / 256, 256>>>(encp, encS, 10);
    gemm_bf16<0><<<dim3(U_ / 64, (B_ * S_) / 128), 256>>>(encS, W1T3, b1, prep, U_, U_, 3072, U_);

    // persistent decoder (single launch, 16 steps)
    dec_persist<<<NB_, 128, DEC_SMEM>>>(W2, b2, dWx, Va, bvp, Ed, teacher, db_in, db_rec);

    // logits = Hall @ Wf + bf
    conv_splitA<<<(T_ * B_ * U_) / 256, 256>>>(Hall, HallS, 10);
    gemm_bf16<1><<<dim3(VP_ / 64, (T_ * B_) / 128), 256>>>(HallS, WfT3, bf, logits_dst, 0, V_, 3072, VP_);

    if (predI || predF) argmax_k<<<T_ * B_, 256>>>(logits_dst, predI, predF, asFloat);
}